// round 3
// baseline (speedup 1.0000x reference)
#include <cuda_runtime.h>
#include <cuda_bf16.h>
#include <math.h>

// ---------------- Problem dims ----------------
#define BB 512
#define TT 512
#define VV 50000
#define EE 100
#define HH 40

typedef unsigned long long u64;

// ---------------- f32x2 packed helpers ----------------
__device__ __forceinline__ u64 f2u2(float x, float y) {
    u64 u; asm("mov.b64 %0, {%1,%2};" : "=l"(u) : "f"(x), "f"(y)); return u;
}
__device__ __forceinline__ u64 fma2(u64 a, u64 b, u64 c) {
    u64 d; asm("fma.rn.f32x2 %0, %1, %2, %3;" : "=l"(d) : "l"(a), "l"(b), "l"(c)); return d;
}
__device__ __forceinline__ u64 add2(u64 a, u64 b) {
    u64 d; asm("add.rn.f32x2 %0, %1, %2;" : "=l"(d) : "l"(a), "l"(b)); return d;
}
__device__ __forceinline__ float2 u2f2(u64 u) {
    float lo, hi; asm("mov.b64 {%0,%1}, %2;" : "=f"(lo), "=f"(hi) : "l"(u));
    return make_float2(lo, hi);
}

__device__ __forceinline__ float sigf(float x) {
    return __fdividef(1.f, 1.f + __expf(-x));
}
__device__ __forceinline__ float tanh_fast(float x) {
    float a = fminf(fmaxf(-2.f * x, -80.f), 80.f);
    float e = __expf(a);
    return __fdividef(1.f - e, 1.f + e);
}

// ---------------- Device scratch ----------------
__device__ __align__(16) float g_embW0[VV * 240];     // layer0 input gates per vocab id
__device__ __align__(16) float g_out0[BB * TT * 80];  // layer0 out, [b][t][fwd40|bwd40]
__device__ __align__(16) float g_gx1[(size_t)BB * TT * 240]; // layer1 precomputed input gates
__device__ __align__(16) float g_Wih0T[EE * 240];
__device__ __align__(16) float g_bih0cat[240];
__device__ __align__(16) float g_Wih1T[80 * 240];
__device__ __align__(16) float g_bih1cat[240];
// pair-packed recurrence weights: P[(k2*120 + j)*2 + c] = W[j][2*k2+c]
__device__ __align__(16) float g_Whh0fP[20 * 120 * 2], g_Whh0bP[20 * 120 * 2];
__device__ __align__(16) float g_Whh1fP[20 * 120 * 2], g_Whh1bP[20 * 120 * 2];
__device__ __align__(16) float g_fc1WT[320 * 128];
__device__ float g_hf0[BB * HH], g_hb0[BB * HH], g_hf1[BB * HH], g_hb1[BB * HH];
__device__ float g_avgp[BB * 80], g_maxp[BB * 80];
__device__ int g_perm[BB];

// ---------------- Prep: transpose / pack all weights ----------------
__global__ void prep_weights(
    const float* __restrict__ Wih0f, const float* __restrict__ Whh0f,
    const float* __restrict__ bih0f,
    const float* __restrict__ Wih0b, const float* __restrict__ Whh0b,
    const float* __restrict__ bih0b,
    const float* __restrict__ Wih1f, const float* __restrict__ Whh1f,
    const float* __restrict__ bih1f,
    const float* __restrict__ Wih1b, const float* __restrict__ Whh1b,
    const float* __restrict__ bih1b,
    const float* __restrict__ fc1_W)
{
    int g = blockIdx.x * blockDim.x + threadIdx.x;
    int NT = gridDim.x * blockDim.x;
    for (int i = g; i < EE * 240; i += NT) {
        int k = i / 240, j = i % 240;
        g_Wih0T[i] = (j < 120) ? Wih0f[j * EE + k] : Wih0b[(j - 120) * EE + k];
    }
    for (int i = g; i < 80 * 240; i += NT) {
        int k = i / 240, j = i % 240;
        g_Wih1T[i] = (j < 120) ? Wih1f[j * 80 + k] : Wih1b[(j - 120) * 80 + k];
    }
    for (int i = g; i < 240; i += NT) {
        g_bih0cat[i] = (i < 120) ? bih0f[i] : bih0b[i - 120];
        g_bih1cat[i] = (i < 120) ? bih1f[i] : bih1b[i - 120];
    }
    for (int i = g; i < 20 * 120 * 2; i += NT) {
        int c = i & 1, t = i >> 1;
        int k2 = t / 120, j = t % 120;
        int src = j * 40 + 2 * k2 + c;
        g_Whh0fP[i] = Whh0f[src];
        g_Whh0bP[i] = Whh0b[src];
        g_Whh1fP[i] = Whh1f[src];
        g_Whh1bP[i] = Whh1b[src];
    }
    for (int i = g; i < 320 * 128; i += NT) {
        int k = i / 128, q = i % 128;
        g_fc1WT[i] = fc1_W[q * 320 + k];
    }
}

// ---------------- Length sort (descending) for load balance ----------------
__global__ void sort_kernel(const int* __restrict__ lens)
{
    __shared__ int L[BB];
    int b = threadIdx.x;
    int lb = lens[b];
    L[b] = lb;
    __syncthreads();
    int r = 0;
    #pragma unroll 8
    for (int i = 0; i < BB; i++) {
        int li = L[i];
        r += (li > lb) || (li == lb && i < b);
    }
    g_perm[r] = b;
}

// ---------------- embW GEMM: [50000,100] x [100,240] + bias (paired rows, fma2) ----------------
__global__ void __launch_bounds__(256) embw_kernel(const float* __restrict__ emb)
{
    int j = threadIdx.x;
    int v0 = blockIdx.x * 64;
    int rows = VV - v0; if (rows > 64) rows = 64;
    __shared__ __align__(16) float A_s[20][68];

    u64 acc[32];
    float bias = (j < 240) ? g_bih0cat[j] : 0.f;
    u64 binit = f2u2(bias, bias);
    #pragma unroll
    for (int i = 0; i < 32; i++) acc[i] = binit;

    for (int k0 = 0; k0 < EE; k0 += 20) {
        __syncthreads();
        for (int idx = threadIdx.x; idx < 64 * 20; idx += 256) {
            int r = idx / 20, k = idx % 20;
            A_s[k][r] = (r < rows) ? emb[(size_t)(v0 + r) * EE + k0 + k] : 0.f;
        }
        __syncthreads();
        if (j < 240) {
            #pragma unroll
            for (int k = 0; k < 20; k++) {
                float wv = g_Wih0T[(k0 + k) * 240 + j];
                u64 ww = f2u2(wv, wv);
                const ulonglong2* ap = (const ulonglong2*)(&A_s[k][0]);
                #pragma unroll
                for (int p = 0; p < 16; p++) {
                    ulonglong2 a = ap[p];
                    acc[2 * p + 0] = fma2(a.x, ww, acc[2 * p + 0]);
                    acc[2 * p + 1] = fma2(a.y, ww, acc[2 * p + 1]);
                }
            }
        }
    }
    if (j < 240) {
        #pragma unroll
        for (int i = 0; i < 32; i++) {
            float2 v = u2f2(acc[i]);
            int r = 2 * i;
            if (r < rows)     g_embW0[(size_t)(v0 + r) * 240 + j] = v.x;
            if (r + 1 < rows) g_embW0[(size_t)(v0 + r + 1) * 240 + j] = v.y;
        }
    }
}

// ---------------- gx1 GEMM: [valid(b,t),80] x [80,240] + bias ----------------
__global__ void __launch_bounds__(256) gx1_kernel(const int* __restrict__ lens)
{
    int b = blockIdx.x;
    int t0 = blockIdx.y * 64;
    int len = lens[b];
    if (t0 >= len) return;
    int rows = len - t0; if (rows > 64) rows = 64;
    int j = threadIdx.x;
    __shared__ __align__(16) float X_s[20][68];

    u64 acc[32];
    float bias = (j < 240) ? g_bih1cat[j] : 0.f;
    u64 binit = f2u2(bias, bias);
    #pragma unroll
    for (int i = 0; i < 32; i++) acc[i] = binit;

    const float* xb = g_out0 + ((size_t)b * TT + t0) * 80;

    for (int k0 = 0; k0 < 80; k0 += 20) {
        __syncthreads();
        for (int idx = threadIdx.x; idx < 64 * 20; idx += 256) {
            int r = idx / 20, k = idx % 20;
            X_s[k][r] = (r < rows) ? xb[r * 80 + k0 + k] : 0.f;
        }
        __syncthreads();
        if (j < 240) {
            #pragma unroll
            for (int k = 0; k < 20; k++) {
                float wv = g_Wih1T[(k0 + k) * 240 + j];
                u64 ww = f2u2(wv, wv);
                const ulonglong2* ap = (const ulonglong2*)(&X_s[k][0]);
                #pragma unroll
                for (int p = 0; p < 16; p++) {
                    ulonglong2 a = ap[p];
                    acc[2 * p + 0] = fma2(a.x, ww, acc[2 * p + 0]);
                    acc[2 * p + 1] = fma2(a.y, ww, acc[2 * p + 1]);
                }
            }
        }
    }
    if (j < 240) {
        float* ob = g_gx1 + ((size_t)b * TT + t0) * 240 + j;
        #pragma unroll
        for (int i = 0; i < 32; i++) {
            float2 v = u2f2(acc[i]);
            int r = 2 * i;
            if (r < rows)     ob[(size_t)r * 240] = v.x;
            if (r + 1 < rows) ob[(size_t)(r + 1) * 240] = v.y;
        }
    }
}

// ---------------- Layer 0 recurrence ----------------
__global__ void __launch_bounds__(128) gru_layer0(
    const int* __restrict__ text, const int* __restrict__ lens,
    const float* __restrict__ bhh0f, const float* __restrict__ bhh0b)
{
    int b = g_perm[blockIdx.x];
    int dir = blockIdx.y;
    int j = threadIdx.x;
    __shared__ __align__(16) float h_s[40];
    __shared__ float srz[80], gxn_s[40], ghn_s[40];
    __shared__ int toks[TT];

    int len = lens[b];
    for (int i = j; i < len; i += 128) toks[i] = text[b * TT + i];

    const u64* wp = (const u64*)(dir ? g_Whh0bP : g_Whh0fP);
    u64 w2[20];
    float bhh_j = 0.f;
    if (j < 120) {
        #pragma unroll
        for (int k2 = 0; k2 < 20; k2++) w2[k2] = wp[k2 * 120 + j];
        bhh_j = (dir ? bhh0b : bhh0f)[j];
    }
    if (j < 40) h_s[j] = 0.f;
    __syncthreads();

    const float* embW = g_embW0 + dir * 120;
    int t0 = dir ? (len - 1) : 0;
    int td = dir ? -1 : 1;

    float gx_cur = 0.f, gx_n1 = 0.f;
    if (j < 120) {
        gx_cur = embW[(size_t)toks[t0] * 240 + j];
        if (len > 1) gx_n1 = embW[(size_t)toks[t0 + td] * 240 + j];
    }

    size_t outbase = ((size_t)b * TT) * 80 + dir * 40 + j;

    for (int s = 0; s < len; s++) {
        int t = t0 + s * td;
        float gx_n2 = 0.f;
        if (j < 120 && s + 2 < len)
            gx_n2 = embW[(size_t)toks[t0 + (s + 2) * td] * 240 + j];
        if (j < 120) {
            u64 a0 = f2u2(bhh_j, 0.f), a1 = 0ull, a2 = 0ull, a3 = 0ull;
            const ulonglong2* h2 = (const ulonglong2*)h_s;
            #pragma unroll
            for (int q = 0; q < 5; q++) {
                ulonglong2 hv = h2[q];
                a0 = fma2(w2[2 * q + 0], hv.x, a0);
                a1 = fma2(w2[2 * q + 1], hv.y, a1);
            }
            #pragma unroll
            for (int q = 5; q < 10; q++) {
                ulonglong2 hv = h2[q];
                a2 = fma2(w2[2 * q + 0], hv.x, a2);
                a3 = fma2(w2[2 * q + 1], hv.y, a3);
            }
            float2 fs = u2f2(add2(add2(a0, a1), add2(a2, a3)));
            float acc = fs.x + fs.y;
            if (j < 80) srz[j] = gx_cur + acc;
            else { gxn_s[j - 80] = gx_cur; ghn_s[j - 80] = acc; }
        }
        __syncthreads();
        if (j < 40) {
            float r = sigf(srz[j]);
            float z = sigf(srz[40 + j]);
            float n = tanh_fast(fmaf(r, ghn_s[j], gxn_s[j]));
            float hn = fmaf(z, h_s[j] - n, n);
            h_s[j] = hn;
            g_out0[outbase + (size_t)t * 80] = hn;
        }
        __syncthreads();
        gx_cur = gx_n1;
        gx_n1 = gx_n2;
    }
    if (j < 40) (dir ? g_hb0 : g_hf0)[b * HH + j] = h_s[j];
}

// ---------------- Layer 1 recurrence (gx precomputed; fused pooling) ----------------
__global__ void __launch_bounds__(128) gru_layer1(
    const int* __restrict__ lens,
    const float* __restrict__ bhh1f, const float* __restrict__ bhh1b)
{
    int b = g_perm[blockIdx.x];
    int dir = blockIdx.y;
    int j = threadIdx.x;
    __shared__ __align__(16) float h_s[40];
    __shared__ float srz[80], gxn_s[40], ghn_s[40];

    int len = lens[b];
    const u64* wp = (const u64*)(dir ? g_Whh1bP : g_Whh1fP);
    u64 w2[20];
    float bhh_j = 0.f;
    if (j < 120) {
        #pragma unroll
        for (int k2 = 0; k2 < 20; k2++) w2[k2] = wp[k2 * 120 + j];
        bhh_j = (dir ? bhh1b : bhh1f)[j];
    }
    if (j < 40) h_s[j] = 0.f;
    __syncthreads();

    int t0 = dir ? (len - 1) : 0;
    int td = dir ? -1 : 1;
    const float* gxb = g_gx1 + ((size_t)b * TT) * 240 + dir * 120 + j;

    float gx_cur = 0.f, gx_n1 = 0.f;
    if (j < 120) {
        gx_cur = gxb[(size_t)t0 * 240];
        if (len > 1) gx_n1 = gxb[(size_t)(t0 + td) * 240];
    }

    float sum_p = 0.f, max_p = -1e30f;

    for (int s = 0; s < len; s++) {
        float gx_n2 = 0.f;
        if (j < 120 && s + 2 < len)
            gx_n2 = gxb[(size_t)(t0 + (s + 2) * td) * 240];
        if (j < 120) {
            u64 a0 = f2u2(bhh_j, 0.f), a1 = 0ull, a2 = 0ull, a3 = 0ull;
            const ulonglong2* h2 = (const ulonglong2*)h_s;
            #pragma unroll
            for (int q = 0; q < 5; q++) {
                ulonglong2 hv = h2[q];
                a0 = fma2(w2[2 * q + 0], hv.x, a0);
                a1 = fma2(w2[2 * q + 1], hv.y, a1);
            }
            #pragma unroll
            for (int q = 5; q < 10; q++) {
                ulonglong2 hv = h2[q];
                a2 = fma2(w2[2 * q + 0], hv.x, a2);
                a3 = fma2(w2[2 * q + 1], hv.y, a3);
            }
            float2 fs = u2f2(add2(add2(a0, a1), add2(a2, a3)));
            float acc = fs.x + fs.y;
            if (j < 80) srz[j] = gx_cur + acc;
            else { gxn_s[j - 80] = gx_cur; ghn_s[j - 80] = acc; }
        }
        __syncthreads();
        if (j < 40) {
            float r = sigf(srz[j]);
            float z = sigf(srz[40 + j]);
            float n = tanh_fast(fmaf(r, ghn_s[j], gxn_s[j]));
            float hn = fmaf(z, h_s[j] - n, n);
            h_s[j] = hn;
            sum_p += hn;
            max_p = fmaxf(max_p, hn);
        }
        __syncthreads();
        gx_cur = gx_n1;
        gx_n1 = gx_n2;
    }
    if (j < 40) {
        g_avgp[b * 80 + dir * 40 + j] = sum_p * __fdividef(1.f, (float)len);
        g_maxp[b * 80 + dir * 40 + j] = max_p;
        (dir ? g_hb1 : g_hf1)[b * HH + j] = h_s[j];
    }
}

// ---------------- Head: pool_cat -> fc1 -> leaky -> fc2 ----------------
__global__ void __launch_bounds__(128) fc_kernel(
    const float* __restrict__ fc1_b, const float* __restrict__ fc2_W,
    const float* __restrict__ fc2_b, float* __restrict__ out)
{
    int b = blockIdx.x, j = threadIdx.x;
    __shared__ float cat[320];
    for (int i = j; i < 320; i += 128) {
        float v;
        if (i < 40)       v = g_hb1[b * 40 + i];
        else if (i < 80)  v = g_hf1[b * 40 + (i - 40)];
        else if (i < 120) v = g_hb0[b * 40 + (i - 80)];
        else if (i < 160) v = g_hf0[b * 40 + (i - 120)];
        else if (i < 240) v = g_avgp[b * 80 + (i - 160)];
        else              v = g_maxp[b * 80 + (i - 240)];
        cat[i] = v;
    }
    __syncthreads();
    float acc = fc1_b[j];
    #pragma unroll 8
    for (int k = 0; k < 320; k++)
        acc = fmaf(g_fc1WT[k * 128 + j], cat[k], acc);
    float h = (acc >= 0.f) ? acc : 0.01f * acc;
    float p = h * fc2_W[j];
    #pragma unroll
    for (int o = 16; o > 0; o >>= 1) p += __shfl_down_sync(0xffffffffu, p, o);
    __shared__ float red[4];
    if ((j & 31) == 0) red[j >> 5] = p;
    __syncthreads();
    if (j == 0) out[b] = (red[0] + red[1] + red[2] + red[3]) + fc2_b[0];
}

// ---------------- Launch ----------------
extern "C" void kernel_launch(void* const* d_in, const int* in_sizes, int n_in,
                              void* d_out, int out_size)
{
    const int*   text     = (const int*)d_in[0];
    const int*   text_len = (const int*)d_in[1];
    const float* emb      = (const float*)d_in[2];
    const float* Wih0f = (const float*)d_in[3];
    const float* Whh0f = (const float*)d_in[4];
    const float* bih0f = (const float*)d_in[5];
    const float* bhh0f = (const float*)d_in[6];
    const float* Wih0b = (const float*)d_in[7];
    const float* Whh0b = (const float*)d_in[8];
    const float* bih0b = (const float*)d_in[9];
    const float* bhh0b = (const float*)d_in[10];
    const float* Wih1f = (const float*)d_in[11];
    const float* Whh1f = (const float*)d_in[12];
    const float* bih1f = (const float*)d_in[13];
    const float* bhh1f = (const float*)d_in[14];
    const float* Wih1b = (const float*)d_in[15];
    const float* Whh1b = (const float*)d_in[16];
    const float* bih1b = (const float*)d_in[17];
    const float* bhh1b = (const float*)d_in[18];
    const float* fc1_W = (const float*)d_in[19];
    const float* fc1_b = (const float*)d_in[20];
    const float* fc2_W = (const float*)d_in[21];
    const float* fc2_b = (const float*)d_in[22];
    float* out = (float*)d_out;

    prep_weights<<<160, 256>>>(Wih0f, Whh0f, bih0f, Wih0b, Whh0b, bih0b,
                               Wih1f, Whh1f, bih1f, Wih1b, Whh1b, bih1b, fc1_W);
    sort_kernel<<<1, BB>>>(text_len);
    embw_kernel<<<(VV + 63) / 64, 256>>>(emb);
    gru_layer0<<<dim3(BB, 2), 128>>>(text, text_len, bhh0f, bhh0b);
    gx1_kernel<<<dim3(BB, TT / 64), 256>>>(text_len);
    gru_layer1<<<dim3(BB, 2), 128>>>(text_len, bhh1f, bhh1b);
    fc_kernel<<<BB, 128>>>(fc1_b, fc2_W, fc2_b, out);
}